// round 6
// baseline (speedup 1.0000x reference)
#include <cuda_runtime.h>
#include <cuda_bf16.h>
#include <math.h>
#include <stdint.h>

#define B_   512
#define T_   256
#define C_   384
#define H_   64
#define BT_  (B_ * T_)

// Scratch Q/K/V stored as tf32 bit patterns (uint32)
__device__ uint32_t g_q[BT_ * H_];
__device__ uint32_t g_k[BT_ * H_];
__device__ uint32_t g_v[BT_ * H_];

// Pre-split weights, bf16x2-packed along k: layout [n(192)][k2(192)]
__device__ uint32_t g_Wh[192 * 192];
__device__ uint32_t g_Wl[192 * 192];

__device__ __forceinline__ uint32_t f2tf(float x) {
    uint32_t u;
    asm("cvt.rna.tf32.f32 %0, %1;" : "=r"(u) : "f"(x));
    return u;
}

__device__ __forceinline__ void mma8(float c[4], const uint32_t a[4], const uint32_t b[2]) {
    asm volatile(
        "mma.sync.aligned.m16n8k8.row.col.f32.tf32.tf32.f32 "
        "{%0,%1,%2,%3},{%4,%5,%6,%7},{%8,%9},{%0,%1,%2,%3};\n"
        : "+f"(c[0]), "+f"(c[1]), "+f"(c[2]), "+f"(c[3])
        : "r"(a[0]), "r"(a[1]), "r"(a[2]), "r"(a[3]), "r"(b[0]), "r"(b[1]));
}

__device__ __forceinline__ void mma16(float c[4], const uint32_t a[4], const uint32_t b[2]) {
    asm volatile(
        "mma.sync.aligned.m16n8k16.row.col.f32.bf16.bf16.f32 "
        "{%0,%1,%2,%3},{%4,%5,%6,%7},{%8,%9},{%0,%1,%2,%3};\n"
        : "+f"(c[0]), "+f"(c[1]), "+f"(c[2]), "+f"(c[3])
        : "r"(a[0]), "r"(a[1]), "r"(a[2]), "r"(a[3]), "r"(b[0]), "r"(b[1]));
}

__device__ __forceinline__ uint32_t packbf(float lo, float hi) {
    __nv_bfloat162 p = __floats2bfloat162_rn(lo, hi);   // x = lo (lower 16)
    return *(uint32_t*)&p;
}
__device__ __forceinline__ float bfr(float x) {
    return __bfloat162float(__float2bfloat16(x));
}

#define CP16(dst_u32, src_ptr) \
    asm volatile("cp.async.cg.shared.global [%0], [%1], 16;\n" \
                 :: "r"(dst_u32), "l"(src_ptr))
#define CP_COMMIT() asm volatile("cp.async.commit_group;\n" ::)
#define CP_WAIT0()  asm volatile("cp.async.wait_group 0;\n" ::)

// ---------------------------------------------------------------------------
// Weight prep: split [Wv|Wk|Wq] (fp32, k-major) into bf16 hi/lo,
// packed bf16x2 along k, layout g_W*[n][k2].
// ---------------------------------------------------------------------------
__global__ __launch_bounds__(512) void prep_w_kernel(
    const float* __restrict__ Wv, const float* __restrict__ Wk,
    const float* __restrict__ Wq)
{
    int idx = blockIdx.x * 512 + threadIdx.x;      // 0..36863
    int k2 = idx / 192;
    int n  = idx - k2 * 192;
    int mtx = n >> 6, lc = n & 63;
    const float* Wm = (mtx == 0) ? Wv : (mtx == 1) ? Wk : Wq;
    float v0 = Wm[(2 * k2) * H_ + lc];
    float v1 = Wm[(2 * k2 + 1) * H_ + lc];
    float h0 = bfr(v0), h1 = bfr(v1);
    g_Wh[n * 192 + k2] = packbf(h0, h1);
    g_Wl[n * 192 + k2] = packbf(v0 - h0, v1 - h1);
}

// ---------------------------------------------------------------------------
// QKV projection via bf16 m16n8k16 3-pass split (Ah*Bh + Ah*Bl + Al*Bh).
// CTA tile 128x192, 512 threads (16 warps, 4x4, warp tile 32x48).
// A: LDG->split->STS (reg prefetch). B: cp.async from pre-split g_Wh/g_Wl.
// ---------------------------------------------------------------------------
#define AHS 20           // A smem stride (uint32 = bf16x2 words), 16 + 4 pad
#define BHS 20           // B smem stride
// smem u32 offsets: Ah0=0 Al0=2560 Ah1=5120 Al1=7680 | Bh0=10240 Bl0=14080
//                   Bh1=17920 Bl1=21760 ; total 25600 u32 = 100.0 KB
#define QKV_SMEM_BYTES (25600 * 4)

__global__ __launch_bounds__(512, 1) void qkv_bf16_kernel(
    const float* __restrict__ inp,
    const float* __restrict__ bv, const float* __restrict__ bk,
    const float* __restrict__ bq)
{
    extern __shared__ uint32_t sm32[];

    const int m0   = blockIdx.x * 128;
    const int tid  = threadIdx.x;
    const int lane = tid & 31;
    const int w    = tid >> 5;
    const int g    = lane >> 2;
    const int t4   = lane & 3;
    const int wm   = w >> 2;          // 0..3 -> 32-row slice
    const int wn   = w & 3;           // 0..3 -> 48-col slice

    const uint32_t sbase = (uint32_t)__cvta_generic_to_shared(sm32);

    // A-load mapping: 1024 float4 / 512 thr = 2 each
    const int ar0 = tid >> 3, ar1 = (tid + 512) >> 3, ac4 = tid & 7;

    // B cp.async mapping: per stage 1536 x 16B (Bh 768 + Bl 768), 3 per thread
    // idx < 768 -> Bh ; else Bl. n = (idx%768)>>2, quad q = idx&3.

    float4 aR[2];
    aR[0] = *(const float4*)&inp[(m0 + ar0) * C_ + ac4 * 4];
    aR[1] = *(const float4*)&inp[(m0 + ar1) * C_ + ac4 * 4];

    // issue B chunk 0
    {
        #pragma unroll
        for (int t = 0; t < 3; t++) {
            int idx = tid + 512 * t;
            int hl  = idx >> 9 > 0 ? (idx - 768 >= 0 ? 1 : 0) : 0; // idx>=768 -> lo
            hl = (idx >= 768) ? 1 : 0;
            int j = idx - hl * 768;
            int n = j >> 2, q = j & 3;
            uint32_t dst = sbase + ((hl ? 14080u : 10240u) + n * BHS + q * 4) * 4;
            const uint32_t* src = (hl ? g_Wl : g_Wh) + n * 192 + q * 4;
            CP16(dst, src);
        }
        CP_COMMIT();
    }

    float acc[2][6][4] = {};

    #pragma unroll 1
    for (int c = 0; c < 12; c++) {
        const int buf = c & 1;

        CP_WAIT0();   // B chunk c landed

        // commit A regs (split to bf16 hi/lo, pack pairs) into buf
        {
            uint32_t* Ah = sm32 + buf * 5120;
            uint32_t* Al = Ah + 2560;
            #pragma unroll
            for (int i = 0; i < 2; i++) {
                int r = i ? ar1 : ar0;
                float4 v = aR[i];
                float hx = bfr(v.x), hy = bfr(v.y), hz = bfr(v.z), hw = bfr(v.w);
                int o = r * AHS + ac4 * 2;
                *(uint2*)&Ah[o] = make_uint2(packbf(hx, hy), packbf(hz, hw));
                *(uint2*)&Al[o] = make_uint2(packbf(v.x - hx, v.y - hy),
                                             packbf(v.z - hz, v.w - hw));
            }
        }
        __syncthreads();

        // prefetch next chunk (A regs + B cp.async)
        if (c + 1 < 12) {
            const int k0n = (c + 1) * 32;
            aR[0] = *(const float4*)&inp[(m0 + ar0) * C_ + k0n + ac4 * 4];
            aR[1] = *(const float4*)&inp[(m0 + ar1) * C_ + k0n + ac4 * 4];
            const int nb = (c + 1) & 1;
            const int kw = (c + 1) * 16;   // k2 offset
            #pragma unroll
            for (int t = 0; t < 3; t++) {
                int idx = tid + 512 * t;
                int hl = (idx >= 768) ? 1 : 0;
                int j = idx - hl * 768;
                int n = j >> 2, q = j & 3;
                uint32_t dst = sbase +
                    ((hl ? 14080u : 10240u) + nb * 7680u + n * BHS + q * 4) * 4;
                const uint32_t* src = (hl ? g_Wl : g_Wh) + n * 192 + kw + q * 4;
                CP16(dst, src);
            }
            CP_COMMIT();
        }

        // compute chunk c: 2 k16 steps x 3 passes
        {
            const uint32_t* Ah = sm32 + buf * 5120;
            const uint32_t* Al = Ah + 2560;
            const uint32_t* Bh = sm32 + 10240 + buf * 7680;
            const uint32_t* Bl = Bh + 3840;

            #pragma unroll
            for (int ks = 0; ks < 2; ks++) {
                const int ko = ks * 8 + t4;
                uint32_t ah[2][4], al[2][4];
                #pragma unroll
                for (int fm = 0; fm < 2; fm++) {
                    int rb = wm * 32 + fm * 16;
                    ah[fm][0] = Ah[(rb + g)     * AHS + ko];
                    ah[fm][1] = Ah[(rb + g + 8) * AHS + ko];
                    ah[fm][2] = Ah[(rb + g)     * AHS + ko + 4];
                    ah[fm][3] = Ah[(rb + g + 8) * AHS + ko + 4];
                    al[fm][0] = Al[(rb + g)     * AHS + ko];
                    al[fm][1] = Al[(rb + g + 8) * AHS + ko];
                    al[fm][2] = Al[(rb + g)     * AHS + ko + 4];
                    al[fm][3] = Al[(rb + g + 8) * AHS + ko + 4];
                }
                #pragma unroll
                for (int fn = 0; fn < 6; fn++) {
                    int n = wn * 48 + fn * 8 + g;
                    uint32_t bh[2], bl[2];
                    bh[0] = Bh[n * BHS + ko];
                    bh[1] = Bh[n * BHS + ko + 4];
                    bl[0] = Bl[n * BHS + ko];
                    bl[1] = Bl[n * BHS + ko + 4];
                    mma16(acc[0][fn], ah[0], bh);
                    mma16(acc[1][fn], ah[1], bh);
                    mma16(acc[0][fn], ah[0], bl);
                    mma16(acc[1][fn], ah[1], bl);
                    mma16(acc[0][fn], al[0], bh);
                    mma16(acc[1][fn], al[1], bh);
                }
            }
        }
        __syncthreads();
    }

    // epilogue: bias add, tf32-round, store
    #pragma unroll
    for (int fm = 0; fm < 2; fm++) {
        int r0 = m0 + wm * 32 + fm * 16 + g;
        #pragma unroll
        for (int fn = 0; fn < 6; fn++) {
            int gcol = wn * 48 + fn * 8 + 2 * t4;
            int mtx  = gcol >> 6;
            int lc   = gcol & 63;
            uint32_t* op = (mtx == 0) ? g_v : (mtx == 1) ? g_k : g_q;
            const float* bp = (mtx == 0) ? bv : (mtx == 1) ? bk : bq;
            float b0f = bp[lc], b1f = bp[lc + 1];
            *(uint2*)&op[r0 * H_ + lc] =
                make_uint2(f2tf(acc[fm][fn][0] + b0f), f2tf(acc[fm][fn][1] + b1f));
            *(uint2*)&op[(r0 + 8) * H_ + lc] =
                make_uint2(f2tf(acc[fm][fn][2] + b0f), f2tf(acc[fm][fn][3] + b1f));
        }
    }
}

// ---------------------------------------------------------------------------
// FlashAttention-2 style attention (unchanged from R4; 72.6 us known-good).
// ---------------------------------------------------------------------------
#define KR_ 68
#define QT_ 68
#define VT_ 72

__global__ __launch_bounds__(256, 2) void attn_fa_kernel(float* __restrict__ out)
{
    extern __shared__ uint32_t sm[];
    uint32_t* Kr = sm;                 // [128][KR_]
    uint32_t* Qt = Kr + 128 * KR_;     // [64][QT_]
    uint32_t* Vs = Qt + 64 * QT_;      // [64][VT_]

    const int b    = blockIdx.x >> 1;
    const int t0   = (blockIdx.x & 1) * 128;
    const int tid  = threadIdx.x;
    const int lane = tid & 31;
    const int w    = tid >> 5;
    const int g    = lane >> 2;
    const int t4   = lane & 3;
    const int m0w  = w * 16;

    const int row0  = t0 + m0w + g;
    const int row1  = row0 + 8;
    const int tlast = t0 + m0w + 15;
    const int jmax  = tlast >> 6;

    const uint32_t* gk = g_k + b * T_ * H_;
    const uint32_t* gq = g_q + b * T_ * H_;
    const uint32_t* gv = g_v + b * T_ * H_;
    const float scale = 0.05103103630798288f;

    #pragma unroll
    for (int i = 0; i < 8; i++) {
        int j = tid + 256 * i;
        int r = j >> 4, h4 = j & 15;
        *(uint4*)&Kr[r * KR_ + h4 * 4] = ((const uint4*)(gk + t0 * H_))[j];
    }

    float m_run0 = -1e30f, m_run1 = -1e30f;
    float l0 = 0.f, l1 = 0.f;
    float accO[8][4] = {};

    const int njt  = (t0 + 128) >> 6;
    const int srcA = (lane & ~3) | (t4 >> 1);
    const int srcB = srcA + 2;
    const int e    = t4 & 1;

    for (int jt = 0; jt < njt; jt++) {
        const int s0 = jt * 64;

        #pragma unroll
        for (int i = 0; i < 4; i++) {
            int j = tid + 256 * i;
            int r = j >> 4, h4 = j & 15;
            *(uint4*)&Qt[r * QT_ + h4 * 4] = ((const uint4*)(gq + s0 * H_))[j];
            *(uint4*)&Vs[r * VT_ + h4 * 4] = ((const uint4*)(gv + s0 * H_))[j];
        }
        __syncthreads();

        if (jt <= jmax) {
            const int nf = min(8, ((tlast - s0) >> 3) + 1);
            const bool need_mask = (s0 + 63 > t0 + m0w);

            float accS[8][4];
            #pragma unroll
            for (int fn = 0; fn < 8; fn++)
                #pragma unroll
                for (int e2 = 0; e2 < 4; e2++) accS[fn][e2] = 0.f;

            #pragma unroll
            for (int ks = 0; ks < 8; ks++) {
                const int k = ks * 8;
                uint32_t a[4];
                a[0] = Kr[(m0w + g)     * KR_ + k + t4];
                a[1] = Kr[(m0w + g + 8) * KR_ + k + t4];
                a[2] = Kr[(m0w + g)     * KR_ + k + t4 + 4];
                a[3] = Kr[(m0w + g + 8) * KR_ + k + t4 + 4];
                for (int fn = 0; fn < nf; fn++) {
                    int n = fn * 8 + g;
                    uint32_t bb[2];
                    bb[0] = Qt[n * QT_ + k + t4];
                    bb[1] = Qt[n * QT_ + k + t4 + 4];
                    mma8(accS[fn], a, bb);
                }
            }

            if (need_mask) {
                for (int fn = 0; fn < nf; fn++) {
                    int c = s0 + fn * 8 + 2 * t4;
                    if (c     > row0) accS[fn][0] = -1e30f;
                    if (c + 1 > row0) accS[fn][1] = -1e30f;
                    if (c     > row1) accS[fn][2] = -1e30f;
                    if (c + 1 > row1) accS[fn][3] = -1e30f;
                }
            }

            float mt0 = -1e30f, mt1 = -1e30f;
            for (int fn = 0; fn < nf; fn++) {
                mt0 = fmaxf(mt0, fmaxf(accS[fn][0], accS[fn][1]));
                mt1 = fmaxf(mt1, fmaxf(accS[fn][2], accS[fn][3]));
            }
            #pragma unroll
            for (int o = 1; o <= 2; o <<= 1) {
                mt0 = fmaxf(mt0, __shfl_xor_sync(0xffffffffu, mt0, o));
                mt1 = fmaxf(mt1, __shfl_xor_sync(0xffffffffu, mt1, o));
            }
            float mn0 = fmaxf(m_run0, mt0);
            float mn1 = fmaxf(m_run1, mt1);
            float al0 = __expf((m_run0 - mn0) * scale);
            float al1 = __expf((m_run1 - mn1) * scale);
            m_run0 = mn0; m_run1 = mn1;

            uint32_t* accU = (uint32_t*)accS;
            float ts0 = 0.f, ts1 = 0.f;
            for (int fn = 0; fn < nf; fn++) {
                float p0 = __expf((accS[fn][0] - mn0) * scale);
                float p1 = __expf((accS[fn][1] - mn0) * scale);
                float p2 = __expf((accS[fn][2] - mn1) * scale);
                float p3 = __expf((accS[fn][3] - mn1) * scale);
                ts0 += p0 + p1; ts1 += p2 + p3;
                accU[fn * 4 + 0] = f2tf(p0);
                accU[fn * 4 + 1] = f2tf(p1);
                accU[fn * 4 + 2] = f2tf(p2);
                accU[fn * 4 + 3] = f2tf(p3);
            }
            #pragma unroll
            for (int o = 1; o <= 2; o <<= 1) {
                ts0 += __shfl_xor_sync(0xffffffffu, ts0, o);
                ts1 += __shfl_xor_sync(0xffffffffu, ts1, o);
            }
            l0 = l0 * al0 + ts0;
            l1 = l1 * al1 + ts1;

            #pragma unroll
            for (int fn = 0; fn < 8; fn++) {
                accO[fn][0] *= al0; accO[fn][1] *= al0;
                accO[fn][2] *= al1; accO[fn][3] *= al1;
            }

            for (int kc = 0; kc < nf; kc++) {
                uint32_t x0 = __shfl_sync(0xffffffffu, accU[kc * 4 + 0], srcA);
                uint32_t x1 = __shfl_sync(0xffffffffu, accU[kc * 4 + 1], srcA);
                uint32_t y0 = __shfl_sync(0xffffffffu, accU[kc * 4 + 2], srcA);
                uint32_t y1 = __shfl_sync(0xffffffffu, accU[kc * 4 + 3], srcA);
                uint32_t x2 = __shfl_sync(0xffffffffu, accU[kc * 4 + 0], srcB);
                uint32_t x3 = __shfl_sync(0xffffffffu, accU[kc * 4 + 1], srcB);
                uint32_t y2 = __shfl_sync(0xffffffffu, accU[kc * 4 + 2], srcB);
                uint32_t y3 = __shfl_sync(0xffffffffu, accU[kc * 4 + 3], srcB);
                uint32_t a[4];
                a[0] = e ? x1 : x0;
                a[1] = e ? y1 : y0;
                a[2] = e ? x3 : x2;
                a[3] = e ? y3 : y2;
                const int k = kc * 8;
                #pragma unroll
                for (int fn = 0; fn < 8; fn++) {
                    int n = fn * 8 + g;
                    uint32_t bb[2];
                    bb[0] = Vs[(k + t4)     * VT_ + n];
                    bb[1] = Vs[(k + t4 + 4) * VT_ + n];
                    mma8(accO[fn], a, bb);
                }
            }
        }
        __syncthreads();
    }

    const float inv0 = 1.0f / l0;
    const float inv1 = 1.0f / l1;
    float* ob = out + (size_t)b * T_ * H_;
    #pragma unroll
    for (int fn = 0; fn < 8; fn++) {
        int c = fn * 8 + 2 * t4;
        *(float2*)&ob[row0 * H_ + c] =
            make_float2(accO[fn][0] * inv0, accO[fn][1] * inv0);
        *(float2*)&ob[row1 * H_ + c] =
            make_float2(accO[fn][2] * inv1, accO[fn][3] * inv1);
    }
}

// ---------------------------------------------------------------------------
extern "C" void kernel_launch(void* const* d_in, const int* in_sizes, int n_in,
                              void* d_out, int out_size)
{
    const float* inp = (const float*)d_in[0];
    const float* Wv  = (const float*)d_in[1];
    const float* bv  = (const float*)d_in[2];
    const float* Wk  = (const float*)d_in[3];
    const float* bk  = (const float*)d_in[4];
    const float* Wq  = (const float*)d_in[5];
    const float* bq  = (const float*)d_in[6];
    float* out = (float*)d_out;

    (void)in_sizes; (void)n_in; (void)out_size;

    // 1) split weights into bf16 hi/lo (tiny)
    prep_w_kernel<<<72, 512>>>(Wv, Wk, Wq);

    // 2) QKV projection (bf16 3-pass mma)
    cudaFuncSetAttribute(qkv_bf16_kernel,
                         cudaFuncAttributeMaxDynamicSharedMemorySize, QKV_SMEM_BYTES);
    qkv_bf16_kernel<<<BT_ / 128, 512, QKV_SMEM_BYTES>>>(inp, bv, bk, bq);

    // 3) attention
    const int attn_smem = (128 * KR_ + 64 * QT_ + 64 * VT_) * 4;
    cudaFuncSetAttribute(attn_fa_kernel,
                         cudaFuncAttributeMaxDynamicSharedMemorySize, attn_smem);
    attn_fa_kernel<<<B_ * 2, 256, attn_smem>>>(out);
}

// round 7
// speedup vs baseline: 1.2771x; 1.2771x over previous
#include <cuda_runtime.h>
#include <math.h>
#include <stdint.h>

#define B_   512
#define T_   256
#define C_   384
#define H_   64
#define BT_  (B_ * T_)

// Scratch Q/K/V stored as tf32 bit patterns (uint32)
__device__ uint32_t g_q[BT_ * H_];
__device__ uint32_t g_k[BT_ * H_];
__device__ uint32_t g_v[BT_ * H_];

__device__ __forceinline__ uint32_t f2tf(float x) {
    uint32_t u;
    asm("cvt.rna.tf32.f32 %0, %1;" : "=r"(u) : "f"(x));
    return u;
}

__device__ __forceinline__ void mma8(float c[4], const uint32_t a[4], const uint32_t b[2]) {
    asm volatile(
        "mma.sync.aligned.m16n8k8.row.col.f32.tf32.tf32.f32 "
        "{%0,%1,%2,%3},{%4,%5,%6,%7},{%8,%9},{%0,%1,%2,%3};\n"
        : "+f"(c[0]), "+f"(c[1]), "+f"(c[2]), "+f"(c[3])
        : "r"(a[0]), "r"(a[1]), "r"(a[2]), "r"(a[3]), "r"(b[0]), "r"(b[1]));
}

#define CP16(dst_u32, src_ptr) \
    asm volatile("cp.async.cg.shared.global [%0], [%1], 16;\n" \
                 :: "r"(dst_u32), "l"(src_ptr))
#define CP_COMMIT() asm volatile("cp.async.commit_group;\n" ::)
#define CP_WAIT1()  asm volatile("cp.async.wait_group 1;\n" ::)
#define CP_WAIT0()  asm volatile("cp.async.wait_group 0;\n" ::)

// ---------------------------------------------------------------------------
// QKV projection (tf32): CTA tile 64x192, 256 threads (8 warps, 2m x 4n,
// warp tile 32x48). 2 CTAs/SM for phase overlap. cp.async double buffer.
// ---------------------------------------------------------------------------
#define AS_ 36    // A smem row stride (floats), 64x32 tile
#define BS_ 200   // B smem row stride (floats), 32x192 tile
#define ASZ (64 * AS_)
#define BSZ (32 * BS_)
#define QKV_SMEM ((2 * ASZ + 2 * BSZ) * 4)

__global__ __launch_bounds__(256, 2) void qkv_mma_kernel(
    const float* __restrict__ inp,
    const float* __restrict__ Wv, const float* __restrict__ bv,
    const float* __restrict__ Wk, const float* __restrict__ bk,
    const float* __restrict__ Wq, const float* __restrict__ bq)
{
    extern __shared__ float smf[];
    float* As = smf;            // [2][ASZ]
    float* Bs = smf + 2 * ASZ;  // [2][BSZ]

    const int m0   = blockIdx.x * 64;
    const int tid  = threadIdx.x;
    const int lane = tid & 31;
    const int w    = tid >> 5;
    const int g    = lane >> 2;
    const int t4   = lane & 3;
    const int wm   = w >> 2;          // 0..1 -> 32-row slice
    const int wn   = w & 3;           // 0..3 -> 48-col slice

    // A: 512 float4 / 256 thr = 2 each
    const int ar0 = tid >> 3, ar1 = (tid + 256) >> 3, ac4 = tid & 7;
    // B: 1536 float4 / 256 thr = 6 each
    int br[6], bm[6], blc4[6];
    #pragma unroll
    for (int i = 0; i < 6; i++) {
        int j = tid + 256 * i;
        br[i] = j / 48;
        int c4 = j % 48;
        bm[i] = c4 >> 4;
        blc4[i] = c4 & 15;
    }
    const float* Ws[3] = { Wv, Wk, Wq };

    const uint32_t sA = (uint32_t)__cvta_generic_to_shared(As);
    const uint32_t sB = (uint32_t)__cvta_generic_to_shared(Bs);

    auto stage = [&](int buf, int k0) {
        uint32_t a_base = sA + buf * ASZ * 4;
        CP16(a_base + (ar0 * AS_ + ac4 * 4) * 4, &inp[(m0 + ar0) * C_ + k0 + ac4 * 4]);
        CP16(a_base + (ar1 * AS_ + ac4 * 4) * 4, &inp[(m0 + ar1) * C_ + k0 + ac4 * 4]);
        uint32_t b_base = sB + buf * BSZ * 4;
        #pragma unroll
        for (int i = 0; i < 6; i++)
            CP16(b_base + (br[i] * BS_ + (bm[i] * 16 + blc4[i]) * 4) * 4,
                 &Ws[bm[i]][(k0 + br[i]) * H_ + blc4[i] * 4]);
    };

    float acc[2][6][4] = {};

    stage(0, 0);
    CP_COMMIT();

    #pragma unroll 1
    for (int it = 0; it < 12; it++) {
        if (it + 1 < 12) { stage((it + 1) & 1, (it + 1) * 32); CP_COMMIT(); CP_WAIT1(); }
        else             { CP_WAIT0(); }
        __syncthreads();

        const float* Af = As + (it & 1) * ASZ;
        const float* Bf = Bs + (it & 1) * BSZ;

        #pragma unroll
        for (int ks = 0; ks < 4; ks++) {
            const int k = ks * 8;
            uint32_t a[2][4];
            #pragma unroll
            for (int fm = 0; fm < 2; fm++) {
                int rb = wm * 32 + fm * 16;
                a[fm][0] = f2tf(Af[(rb + g)     * AS_ + k + t4]);
                a[fm][1] = f2tf(Af[(rb + g + 8) * AS_ + k + t4]);
                a[fm][2] = f2tf(Af[(rb + g)     * AS_ + k + t4 + 4]);
                a[fm][3] = f2tf(Af[(rb + g + 8) * AS_ + k + t4 + 4]);
            }
            #pragma unroll
            for (int fn = 0; fn < 6; fn++) {
                int n = wn * 48 + fn * 8 + g;
                uint32_t b[2];
                b[0] = f2tf(Bf[(k + t4)     * BS_ + n]);
                b[1] = f2tf(Bf[(k + t4 + 4) * BS_ + n]);
                mma8(acc[0][fn], a[0], b);
                mma8(acc[1][fn], a[1], b);
            }
        }
        __syncthreads();
    }

    // epilogue: bias add, tf32-round, store
    #pragma unroll
    for (int fm = 0; fm < 2; fm++) {
        int r0 = m0 + wm * 32 + fm * 16 + g;
        #pragma unroll
        for (int fn = 0; fn < 6; fn++) {
            int gcol = wn * 48 + fn * 8 + 2 * t4;
            int mtx  = gcol >> 6;
            int lc   = gcol & 63;
            uint32_t* op = (mtx == 0) ? g_v : (mtx == 1) ? g_k : g_q;
            const float* bp = (mtx == 0) ? bv : (mtx == 1) ? bk : bq;
            float b0f = bp[lc], b1f = bp[lc + 1];
            *(uint2*)&op[r0 * H_ + lc] =
                make_uint2(f2tf(acc[fm][fn][0] + b0f), f2tf(acc[fm][fn][1] + b1f));
            *(uint2*)&op[(r0 + 8) * H_ + lc] =
                make_uint2(f2tf(acc[fm][fn][2] + b0f), f2tf(acc[fm][fn][3] + b1f));
        }
    }
}

// ---------------------------------------------------------------------------
// FlashAttention-2 style attention (unchanged; 72.6 us known-good).
// ---------------------------------------------------------------------------
#define KR_ 68
#define QT_ 68
#define VT_ 72

__global__ __launch_bounds__(256, 2) void attn_fa_kernel(float* __restrict__ out)
{
    extern __shared__ uint32_t sm[];
    uint32_t* Kr = sm;                 // [128][KR_]
    uint32_t* Qt = Kr + 128 * KR_;     // [64][QT_]
    uint32_t* Vs = Qt + 64 * QT_;      // [64][VT_]

    const int b    = blockIdx.x >> 1;
    const int t0   = (blockIdx.x & 1) * 128;
    const int tid  = threadIdx.x;
    const int lane = tid & 31;
    const int w    = tid >> 5;
    const int g    = lane >> 2;
    const int t4   = lane & 3;
    const int m0w  = w * 16;

    const int row0  = t0 + m0w + g;
    const int row1  = row0 + 8;
    const int tlast = t0 + m0w + 15;
    const int jmax  = tlast >> 6;

    const uint32_t* gk = g_k + b * T_ * H_;
    const uint32_t* gq = g_q + b * T_ * H_;
    const uint32_t* gv = g_v + b * T_ * H_;
    const float scale = 0.05103103630798288f;

    #pragma unroll
    for (int i = 0; i < 8; i++) {
        int j = tid + 256 * i;
        int r = j >> 4, h4 = j & 15;
        *(uint4*)&Kr[r * KR_ + h4 * 4] = ((const uint4*)(gk + t0 * H_))[j];
    }

    float m_run0 = -1e30f, m_run1 = -1e30f;
    float l0 = 0.f, l1 = 0.f;
    float accO[8][4] = {};

    const int njt  = (t0 + 128) >> 6;
    const int srcA = (lane & ~3) | (t4 >> 1);
    const int srcB = srcA + 2;
    const int e    = t4 & 1;

    for (int jt = 0; jt < njt; jt++) {
        const int s0 = jt * 64;

        #pragma unroll
        for (int i = 0; i < 4; i++) {
            int j = tid + 256 * i;
            int r = j >> 4, h4 = j & 15;
            *(uint4*)&Qt[r * QT_ + h4 * 4] = ((const uint4*)(gq + s0 * H_))[j];
            *(uint4*)&Vs[r * VT_ + h4 * 4] = ((const uint4*)(gv + s0 * H_))[j];
        }
        __syncthreads();

        if (jt <= jmax) {
            const int nf = min(8, ((tlast - s0) >> 3) + 1);
            const bool need_mask = (s0 + 63 > t0 + m0w);

            float accS[8][4];
            #pragma unroll
            for (int fn = 0; fn < 8; fn++)
                #pragma unroll
                for (int e2 = 0; e2 < 4; e2++) accS[fn][e2] = 0.f;

            #pragma unroll
            for (int ks = 0; ks < 8; ks++) {
                const int k = ks * 8;
                uint32_t a[4];
                a[0] = Kr[(m0w + g)     * KR_ + k + t4];
                a[1] = Kr[(m0w + g + 8) * KR_ + k + t4];
                a[2] = Kr[(m0w + g)     * KR_ + k + t4 + 4];
                a[3] = Kr[(m0w + g + 8) * KR_ + k + t4 + 4];
                for (int fn = 0; fn < nf; fn++) {
                    int n = fn * 8 + g;
                    uint32_t bb[2];
                    bb[0] = Qt[n * QT_ + k + t4];
                    bb[1] = Qt[n * QT_ + k + t4 + 4];
                    mma8(accS[fn], a, bb);
                }
            }

            if (need_mask) {
                for (int fn = 0; fn < nf; fn++) {
                    int c = s0 + fn * 8 + 2 * t4;
                    if (c     > row0) accS[fn][0] = -1e30f;
                    if (c + 1 > row0) accS[fn][1] = -1e30f;
                    if (c     > row1) accS[fn][2] = -1e30f;
                    if (c + 1 > row1) accS[fn][3] = -1e30f;
                }
            }

            float mt0 = -1e30f, mt1 = -1e30f;
            for (int fn = 0; fn < nf; fn++) {
                mt0 = fmaxf(mt0, fmaxf(accS[fn][0], accS[fn][1]));
                mt1 = fmaxf(mt1, fmaxf(accS[fn][2], accS[fn][3]));
            }
            #pragma unroll
            for (int o = 1; o <= 2; o <<= 1) {
                mt0 = fmaxf(mt0, __shfl_xor_sync(0xffffffffu, mt0, o));
                mt1 = fmaxf(mt1, __shfl_xor_sync(0xffffffffu, mt1, o));
            }
            float mn0 = fmaxf(m_run0, mt0);
            float mn1 = fmaxf(m_run1, mt1);
            float al0 = __expf((m_run0 - mn0) * scale);
            float al1 = __expf((m_run1 - mn1) * scale);
            m_run0 = mn0; m_run1 = mn1;

            uint32_t* accU = (uint32_t*)accS;
            float ts0 = 0.f, ts1 = 0.f;
            for (int fn = 0; fn < nf; fn++) {
                float p0 = __expf((accS[fn][0] - mn0) * scale);
                float p1 = __expf((accS[fn][1] - mn0) * scale);
                float p2 = __expf((accS[fn][2] - mn1) * scale);
                float p3 = __expf((accS[fn][3] - mn1) * scale);
                ts0 += p0 + p1; ts1 += p2 + p3;
                accU[fn * 4 + 0] = f2tf(p0);
                accU[fn * 4 + 1] = f2tf(p1);
                accU[fn * 4 + 2] = f2tf(p2);
                accU[fn * 4 + 3] = f2tf(p3);
            }
            #pragma unroll
            for (int o = 1; o <= 2; o <<= 1) {
                ts0 += __shfl_xor_sync(0xffffffffu, ts0, o);
                ts1 += __shfl_xor_sync(0xffffffffu, ts1, o);
            }
            l0 = l0 * al0 + ts0;
            l1 = l1 * al1 + ts1;

            #pragma unroll
            for (int fn = 0; fn < 8; fn++) {
                accO[fn][0] *= al0; accO[fn][1] *= al0;
                accO[fn][2] *= al1; accO[fn][3] *= al1;
            }

            for (int kc = 0; kc < nf; kc++) {
                uint32_t x0 = __shfl_sync(0xffffffffu, accU[kc * 4 + 0], srcA);
                uint32_t x1 = __shfl_sync(0xffffffffu, accU[kc * 4 + 1], srcA);
                uint32_t y0 = __shfl_sync(0xffffffffu, accU[kc * 4 + 2], srcA);
                uint32_t y1 = __shfl_sync(0xffffffffu, accU[kc * 4 + 3], srcA);
                uint32_t x2 = __shfl_sync(0xffffffffu, accU[kc * 4 + 0], srcB);
                uint32_t x3 = __shfl_sync(0xffffffffu, accU[kc * 4 + 1], srcB);
                uint32_t y2 = __shfl_sync(0xffffffffu, accU[kc * 4 + 2], srcB);
                uint32_t y3 = __shfl_sync(0xffffffffu, accU[kc * 4 + 3], srcB);
                uint32_t a[4];
                a[0] = e ? x1 : x0;
                a[1] = e ? y1 : y0;
                a[2] = e ? x3 : x2;
                a[3] = e ? y3 : y2;
                const int k = kc * 8;
                #pragma unroll
                for (int fn = 0; fn < 8; fn++) {
                    int n = fn * 8 + g;
                    uint32_t bb[2];
                    bb[0] = Vs[(k + t4)     * VT_ + n];
                    bb[1] = Vs[(k + t4 + 4) * VT_ + n];
                    mma8(accO[fn], a, bb);
                }
            }
        }
        __syncthreads();
    }

    const float inv0 = 1.0f / l0;
    const float inv1 = 1.0f / l1;
    float* ob = out + (size_t)b * T_ * H_;
    #pragma unroll
    for (int fn = 0; fn < 8; fn++) {
        int c = fn * 8 + 2 * t4;
        *(float2*)&ob[row0 * H_ + c] =
            make_float2(accO[fn][0] * inv0, accO[fn][1] * inv0);
        *(float2*)&ob[row1 * H_ + c] =
            make_float2(accO[fn][2] * inv1, accO[fn][3] * inv1);
    }
}

// ---------------------------------------------------------------------------
extern "C" void kernel_launch(void* const* d_in, const int* in_sizes, int n_in,
                              void* d_out, int out_size)
{
    const float* inp = (const float*)d_in[0];
    const float* Wv  = (const float*)d_in[1];
    const float* bv  = (const float*)d_in[2];
    const float* Wk  = (const float*)d_in[3];
    const float* bk  = (const float*)d_in[4];
    const float* Wq  = (const float*)d_in[5];
    const float* bq  = (const float*)d_in[6];
    float* out = (float*)d_out;

    (void)in_sizes; (void)n_in; (void)out_size;

    cudaFuncSetAttribute(qkv_mma_kernel,
                         cudaFuncAttributeMaxDynamicSharedMemorySize, QKV_SMEM);
    qkv_mma_kernel<<<BT_ / 64, 256, QKV_SMEM>>>(inp, Wv, bv, Wk, bk, Wq, bq);

    const int attn_smem = (128 * KR_ + 64 * QT_ + 64 * VT_) * 4;
    cudaFuncSetAttribute(attn_fa_kernel,
                         cudaFuncAttributeMaxDynamicSharedMemorySize, attn_smem);
    attn_fa_kernel<<<B_ * 2, 256, attn_smem>>>(out);
}